// round 2
// baseline (speedup 1.0000x reference)
#include <cuda_runtime.h>

// Problem shape (fixed by dataset)
constexpr int B = 1024;   // rows of x
constexpr int O = 256;    // rows of basis (centroids)
constexpr int D = 1024;   // feature dim

// Tiling
constexpr int BM = 64;    // x rows per block
constexpr int BN = 32;    // basis rows per block
constexpr int BK = 64;    // k-chunk
constexpr int TM = 4;     // x rows per thread
constexpr int TN = 2;     // basis rows per thread
constexpr int XP = BK + 4; // 68: xs row stride, 16B-aligned rows (68*4 % 16 == 0)
constexpr int BP = BK + 1; // 65: bs row stride, odd -> conflict-free strided reads

constexpr float ALPHA = 0.005f;

// Kernel 1: xd[b,o] = sum_d |x-c| + 0.5*sqrt(sum_d (x-c)^2)
__global__ __launch_bounds__(256, 1) void CDR_dist_kernel(
    const float* __restrict__ x,
    const float* __restrict__ basis,
    float* __restrict__ xd)
{
    __shared__ float xs[BM][XP];
    __shared__ float bs[BN][BP];

    const int tid = threadIdx.x;
    const int tx  = tid & 15;   // 16 threads across N
    const int ty  = tid >> 4;   // 16 threads across M
    const int bm  = blockIdx.x * BM;
    const int bn  = blockIdx.y * BN;

    float acc1[TM][TN];
    float acc2[TM][TN];
#pragma unroll
    for (int i = 0; i < TM; i++)
#pragma unroll
        for (int j = 0; j < TN; j++) { acc1[i][j] = 0.0f; acc2[i][j] = 0.0f; }

    for (int k0 = 0; k0 < D; k0 += BK) {
        // Load x tile: BM x BK = 4096 floats = 1024 float4, 4 per thread.
        // idx -> (row = idx/16, col4 = idx%16). float4 smem stores (rows 16B-aligned).
#pragma unroll
        for (int t = 0; t < 4; t++) {
            int idx = tid + t * 256;
            int r = idx >> 4;
            int c = (idx & 15) << 2;
            float4 v = *reinterpret_cast<const float4*>(&x[(size_t)(bm + r) * D + k0 + c]);
            *reinterpret_cast<float4*>(&xs[r][c]) = v;
        }
        // Load basis tile: BN x BK = 2048 floats = 512 float4, 2 per thread.
        // bs rows have odd stride -> scalar stores.
#pragma unroll
        for (int t = 0; t < 2; t++) {
            int idx = tid + t * 256;
            int r = idx >> 4;
            int c = (idx & 15) << 2;
            float4 v = *reinterpret_cast<const float4*>(&basis[(size_t)(bn + r) * D + k0 + c]);
            bs[r][c + 0] = v.x;
            bs[r][c + 1] = v.y;
            bs[r][c + 2] = v.z;
            bs[r][c + 3] = v.w;
        }
        __syncthreads();

#pragma unroll 8
        for (int k = 0; k < BK; k++) {
            float xv[TM];
            float bv[TN];
#pragma unroll
            for (int i = 0; i < TM; i++) xv[i] = xs[ty * TM + i][k];   // 2 addrs/warp: broadcast
#pragma unroll
            for (int j = 0; j < TN; j++) bv[j] = bs[tx * TN + j][k];   // odd stride: conflict-free
#pragma unroll
            for (int i = 0; i < TM; i++)
#pragma unroll
                for (int j = 0; j < TN; j++) {
                    float d = xv[i] - bv[j];
                    acc1[i][j] += fabsf(d);                 // FADD with |src| modifier
                    acc2[i][j] = fmaf(d, d, acc2[i][j]);    // FFMA
                }
        }
        __syncthreads();
    }

    // Epilogue: xd = L1 + L2/2  (T = (1, 2))
#pragma unroll
    for (int i = 0; i < TM; i++)
#pragma unroll
        for (int j = 0; j < TN; j++) {
            int m = bm + ty * TM + i;
            int n = bn + tx * TN + j;
            xd[(size_t)m * O + n] = acc1[i][j] + 0.5f * sqrtf(acc2[i][j]);
        }
}

// Kernel 2: in-place alpha correction + negation.
// out[b,o] = -( xd*(1+a) - S*a ) = a*S - (1+a)*xd   with S = row sum over o.
__global__ __launch_bounds__(256, 1) void CDR_alpha_kernel(float* __restrict__ xd)
{
    const int b = blockIdx.x;
    const int o = threadIdx.x;   // 256 threads == O
    float v = xd[(size_t)b * O + o];

    __shared__ float warp_s[8];
    float s = v;
#pragma unroll
    for (int off = 16; off > 0; off >>= 1)
        s += __shfl_xor_sync(0xffffffffu, s, off);
    if ((o & 31) == 0) warp_s[o >> 5] = s;
    __syncthreads();

    float S = warp_s[0] + warp_s[1] + warp_s[2] + warp_s[3]
            + warp_s[4] + warp_s[5] + warp_s[6] + warp_s[7];

    xd[(size_t)b * O + o] = ALPHA * S - (1.0f + ALPHA) * v;
}

extern "C" void kernel_launch(void* const* d_in, const int* in_sizes, int n_in,
                              void* d_out, int out_size)
{
    const float* x     = (const float*)d_in[0];
    const float* basis = (const float*)d_in[1];
    float* out = (float*)d_out;

    dim3 grid1(B / BM, O / BN);   // 16 x 8 = 128 blocks
    CDR_dist_kernel<<<grid1, 256>>>(x, basis, out);
    CDR_alpha_kernel<<<B, 256>>>(out);
}